// round 16
// baseline (speedup 1.0000x reference)
#include <cuda_runtime.h>

#define BB 256
#define TT 512
#define DD 50
#define HH 128
#define G4 512
#define HID 256

typedef unsigned long long ull;

// ---- device scratch ----
__device__ float g_xgT[2][TT][G4][BB];   // input-gate preactivations [d][t][row][b]

__device__ __forceinline__ float sigf(float x)   { return 1.0f / (1.0f + __expf(-x)); }
__device__ __forceinline__ float tanhf_(float x) { return 2.0f / (1.0f + __expf(-2.0f * x)) - 1.0f; }

__device__ __forceinline__ ull pack2(float a, float b) {
    ull r; asm("mov.b64 %0,{%1,%2};" : "=l"(r) : "f"(a), "f"(b)); return r;
}
__device__ __forceinline__ void unpack2(ull v, float& a, float& b) {
    asm("mov.b64 {%0,%1},%2;" : "=f"(a), "=f"(b) : "l"(v));
}
__device__ __forceinline__ void fma2(ull a, ull b, ull& c) {
    asm("fma.rn.f32x2 %0,%1,%2,%0;" : "+l"(c) : "l"(a), "l"(b));
}
__device__ __forceinline__ ull add2(ull a, ull b) {
    ull r; asm("add.rn.f32x2 %0,%1,%2;" : "=l"(r) : "l"(a), "l"(b)); return r;
}
__device__ __forceinline__ unsigned smem_u32(const void* p) {
    unsigned r;
    asm("{ .reg .u64 t; cvta.to.shared.u64 t, %1; cvt.u32.u64 %0, t; }" : "=r"(r) : "l"(p));
    return r;
}

// ---------------------------------------------------------------------------
// Embedding lookup + input-gate GEMM -> transposed xg (unchanged)
// ---------------------------------------------------------------------------
__global__ void __launch_bounds__(256) embed_gemm(
    const int*   __restrict__ idx,
    const float* __restrict__ emb,
    const float* __restrict__ Wih_f, const float* __restrict__ bih_f, const float* __restrict__ bhh_f,
    const float* __restrict__ Wih_b, const float* __restrict__ bih_b, const float* __restrict__ bhh_b)
{
    __shared__ __align__(16) float xsA[16 * DD * 2];
    const int tid = threadIdx.x;
    const int b0  = blockIdx.x * 32;
    const int t   = blockIdx.y;

    for (int i = tid; i < 32 * DD; i += 256) {
        int b = i / DD, k = i - b * DD;
        int id = idx[(b0 + b) * TT + t];
        xsA[(b >> 1) * (2 * DD) + k * 2 + (b & 1)] = emb[id * DD + k];
    }
    __syncthreads();

    #pragma unroll 1
    for (int g = 0; g < 4; ++g) {
        int col = tid + g * 256;
        int dir = col >> 9;
        int n   = col & 511;
        const float* W = dir ? Wih_b : Wih_f;
        float bias = dir ? (bih_b[n] + bhh_b[n]) : (bih_f[n] + bhh_f[n]);

        float w[DD];
        #pragma unroll
        for (int k = 0; k < DD; ++k) w[k] = W[n * DD + k];

        ull acc[16];
        ull bp2 = pack2(bias, bias);
        #pragma unroll
        for (int p = 0; p < 16; ++p) acc[p] = bp2;

        #pragma unroll 2
        for (int k = 0; k < DD; ++k) {
            ull w2 = pack2(w[k], w[k]);
            #pragma unroll
            for (int p = 0; p < 16; ++p) {
                ull x = *(const ull*)&xsA[p * (2 * DD) + k * 2];
                fma2(x, w2, acc[p]);
            }
        }

        float* dst = &g_xgT[dir][t][n][b0];
        #pragma unroll
        for (int p = 0; p < 16; ++p) {
            float a, b; unpack2(acc[p], a, b);
            *(float2*)&dst[2 * p] = make_float2(a, b);
        }
    }
}

// ---------------------------------------------------------------------------
// Persistent LSTM recurrence (R12 shell + gate-paired weights, duplicated h).
// grid (4 kq, 32 bt, 2 dir) = 256 CTAs x 256 threads, cluster (4,1,1), 2 CTA/SM.
// Thread (kk = warp*4 + (lane&3) in 0..31, kgrp = lane>>2): owns all 4 gates of
// its k-output over a 16-k input slice x 8 batches.
//   weights: pre-packed (wi,wf),(wg,wo) ull pairs in regs (64 regs, NO loop MOVs)
//   h: stored DUPLICATED (h,h) per (k,b) -> LDS.128 yields ready FFMA2 operands
//   inner loop: 4 LDS.128 + 16 FFMA2, zero MOVs
// h layout: slice (16 rows) per kgrp; row stride 20 words (16B-aligned),
// slice stride 324 words (banks rotate by 4 per kgrp -> conflict-free).
// Row position q holds batch b = q ^ (k>>4); butterfly narrows over q=b^kgrp:
//   r1 xor16: A[p][q] += shfl(A[p][q^4]) (q=0..3); r2 xor8: q^2; r3 xor4: q^1.
// Final A[p][0] = batch kgrp -> every thread updates exactly one (k,b).
// ---------------------------------------------------------------------------
#define ROW_W  20                  // words per k-row (8 dup-pairs + 4 pad)
#define SL_W   324                 // words per 16-row slice (16*20 + 4)
#define HBD_W  (8 * SL_W)          // 2592 words per parity buffer

__global__ void __launch_bounds__(256, 2) __cluster_dims__(4, 1, 1)
lstm_gp(const float* __restrict__ Whh_f, const float* __restrict__ Whh_b,
        const float* __restrict__ masks, float* __restrict__ out)
{
    __shared__ __align__(16) float hb[2][HBD_W];

    const int tid  = threadIdx.x;
    const int kq   = blockIdx.x;             // k-quarter == cluster rank
    const int bt   = blockIdx.y;
    const int d    = blockIdx.z;
    const int K0   = kq * 32;
    const int bb0  = bt * 8;
    const int lane = tid & 31;
    const int warp = tid >> 5;

    const int kkl   = lane & 3;
    const int kgrp  = lane >> 2;             // 0..7
    const int kk    = warp * 4 + kkl;        // 0..31
    const int kglob = K0 + kk;
    const int bu    = bb0 + kgrp;            // owned batch

    const float* Whh = d ? Whh_b : Whh_f;

    // ---- weights: gate-paired ull (wi,wf),(wg,wo) per own 16-k slice ----
    ull wif[16], wgo[16];
    #pragma unroll
    for (int i = 0; i < 16; ++i) {
        int kin = kgrp * 16 + i;
        float wi = __ldg(&Whh[(0 * 128 + kglob) * 128 + kin]);
        float wf = __ldg(&Whh[(1 * 128 + kglob) * 128 + kin]);
        float wg = __ldg(&Whh[(2 * 128 + kglob) * 128 + kin]);
        float wo = __ldg(&Whh[(3 * 128 + kglob) * 128 + kin]);
        wif[i] = pack2(wi, wf);
        wgo[i] = pack2(wg, wo);
    }

    // zero h buffer 0
    for (int i = tid; i < HBD_W; i += 256) hb[0][i] = 0.f;

    // ---- h store word: row kglob, slot q = b ^ (kglob>>4), duplicated 8B ----
    const int hsl = kglob >> 4;                       // slice of this k-row
    const int qw  = (kgrp ^ hsl) & 7;
    const int hw  = hsl * SL_W + (kglob & 15) * ROW_W + qw * 2;
    char* lbase = (char*)&hb[0][0] + hw * 4;
    const unsigned par_off = (unsigned)(HBD_W * 4);   // hb[1] - hb[0] bytes
    unsigned rem0[3];
    {
        unsigned a0 = smem_u32(&hb[0][0]) + (unsigned)(hw * 4);
        #pragma unroll
        for (int p = 0; p < 3; ++p) {
            unsigned pr = (kq + 1 + p) & 3;
            asm("mapa.shared::cluster.u32 %0, %1, %2;" : "=r"(rem0[p]) : "r"(a0), "r"(pr));
        }
    }

    // ---- per-thread state ----
    float c = 0.f, m = -3.0e38f;

    const int tstep = d ? -1 : 1;
    int t = d ? (TT - 1) : 0;

    // prefetch xg (4 gate rows, own batch) + mask penalty for step 0
    float xn0, xn1, xn2, xn3, pen;
    {
        const float* p = &g_xgT[d][t][0][bu];
        xn0 = __ldg(p + (0 * 128 + kglob) * BB);
        xn1 = __ldg(p + (1 * 128 + kglob) * BB);
        xn2 = __ldg(p + (2 * 128 + kglob) * BB);
        xn3 = __ldg(p + (3 * 128 + kglob) * BB);
        pen = (1.0f - __ldg(&masks[bu * TT + t])) * 1e8f;
    }

    __syncthreads();   // hb[0] zeroed (local); peers independent

    int cur = 0;
    for (int s = 0; s < TT; ++s) {
        float cx0 = xn0, cx1 = xn1, cx2 = xn2, cx3 = xn3, cpen = pen;
        // prefetch next step (issues before the barrier wait below)
        {
            int t2 = t + tstep;
            t2 = (t2 < 0) ? 0 : (t2 > TT - 1 ? TT - 1 : t2);
            const float* p = &g_xgT[d][t2][0][bu];
            xn0 = __ldg(p + (0 * 128 + kglob) * BB);
            xn1 = __ldg(p + (1 * 128 + kglob) * BB);
            xn2 = __ldg(p + (2 * 128 + kglob) * BB);
            xn3 = __ldg(p + (3 * 128 + kglob) * BB);
            pen = (1.0f - __ldg(&masks[bu * TT + t2])) * 1e8f;
        }

        // complete last step's h exchange (arrive happened after the pushes)
        if (s > 0) {
            asm volatile("barrier.cluster.wait.aligned;" ::: "memory");
        }

        // ---- MAC: own 16-k slice; 4 LDS.128 + 16 FFMA2 per iter, no MOVs ----
        ull A[2][8];   // [gate-pair][q-slot]
        #pragma unroll
        for (int p = 0; p < 2; ++p)
            #pragma unroll
            for (int q = 0; q < 8; ++q) A[p][q] = 0ull;

        const float* hc = &hb[cur][kgrp * SL_W];
        #pragma unroll
        for (int i = 0; i < 16; ++i) {
            const ull* r = (const ull*)(hc + i * ROW_W);
            ulonglong2 H0 = *(const ulonglong2*)(r + 0);   // q0, q1 (dup pairs)
            ulonglong2 H1 = *(const ulonglong2*)(r + 2);   // q2, q3
            ulonglong2 H2 = *(const ulonglong2*)(r + 4);   // q4, q5
            ulonglong2 H3 = *(const ulonglong2*)(r + 6);   // q6, q7
            ull a = wif[i], b = wgo[i];
            fma2(H0.x, a, A[0][0]); fma2(H0.x, b, A[1][0]);
            fma2(H0.y, a, A[0][1]); fma2(H0.y, b, A[1][1]);
            fma2(H1.x, a, A[0][2]); fma2(H1.x, b, A[1][2]);
            fma2(H1.y, a, A[0][3]); fma2(H1.y, b, A[1][3]);
            fma2(H2.x, a, A[0][4]); fma2(H2.x, b, A[1][4]);
            fma2(H2.y, a, A[0][5]); fma2(H2.y, b, A[1][5]);
            fma2(H3.x, a, A[0][6]); fma2(H3.x, b, A[1][6]);
            fma2(H3.y, a, A[0][7]); fma2(H3.y, b, A[1][7]);
        }

        // ---- narrowing butterfly over kgrp (14 SHFL + 14 add2) ----
        #pragma unroll
        for (int p = 0; p < 2; ++p) {
            #pragma unroll
            for (int q = 0; q < 4; ++q)
                A[p][q] = add2(A[p][q], __shfl_xor_sync(0xffffffffu, A[p][q + 4], 16));
            A[p][0] = add2(A[p][0], __shfl_xor_sync(0xffffffffu, A[p][2], 8));
            A[p][1] = add2(A[p][1], __shfl_xor_sync(0xffffffffu, A[p][3], 8));
            A[p][0] = add2(A[p][0], __shfl_xor_sync(0xffffffffu, A[p][1], 4));
        }

        // ---- update: thread owns (kglob, bu) exactly ----
        float gi, gf, gg, go;
        unpack2(A[0][0], gi, gf);
        unpack2(A[1][0], gg, go);
        gi += cx0; gf += cx1; gg += cx2; go += cx3;

        c = sigf(gf) * c + sigf(gi) * tanhf_(gg);
        float hv = sigf(go) * tanhf_(c);
        m = fmaxf(m, hv - cpen);

        if (s < TT - 1) {
            // push duplicated (hv,hv): local + 3 DSMEM peers (8B each)
            unsigned nb = cur ? 0u : par_off;
            asm volatile("st.shared.v2.f32 [%0], {%1,%2};"
                         :: "r"(smem_u32(lbase) + nb), "f"(hv), "f"(hv) : "memory");
            asm volatile("st.shared::cluster.v2.f32 [%0], {%1,%2};"
                         :: "r"(rem0[0] + nb), "f"(hv), "f"(hv) : "memory");
            asm volatile("st.shared::cluster.v2.f32 [%0], {%1,%2};"
                         :: "r"(rem0[1] + nb), "f"(hv), "f"(hv) : "memory");
            asm volatile("st.shared::cluster.v2.f32 [%0], {%1,%2};"
                         :: "r"(rem0[2] + nb), "f"(hv), "f"(hv) : "memory");
            // release our pushes; wait happens after next step's prefetch
            asm volatile("barrier.cluster.arrive.aligned;" ::: "memory");
        }

        cur ^= 1;
        t += tstep;
    }

    out[bu * HID + d * HH + kglob] = m;
}

// ---------------------------------------------------------------------------
extern "C" void kernel_launch(void* const* d_in, const int* in_sizes, int n_in,
                              void* d_out, int out_size)
{
    (void)in_sizes; (void)n_in; (void)out_size;
    const int*   idx   = (const int*)  d_in[0];
    const float* masks = (const float*)d_in[1];
    const float* emb   = (const float*)d_in[2];
    const float* Wih_f = (const float*)d_in[3];
    const float* Whh_f = (const float*)d_in[4];
    const float* bih_f = (const float*)d_in[5];
    const float* bhh_f = (const float*)d_in[6];
    const float* Wih_b = (const float*)d_in[7];
    const float* Whh_b = (const float*)d_in[8];
    const float* bih_b = (const float*)d_in[9];
    const float* bhh_b = (const float*)d_in[10];
    float* out = (float*)d_out;

    embed_gemm<<<dim3(8, TT), 256>>>(idx, emb, Wih_f, bih_f, bhh_f,
                                     Wih_b, bih_b, bhh_b);
    lstm_gp<<<dim3(4, 32, 2), 256>>>(Whh_f, Whh_b, masks, out);
}